// round 1
// baseline (speedup 1.0000x reference)
#include <cuda_runtime.h>
#include <math.h>

#define D    128
#define D4   32
#define NMAX 50000
#define BK   16
#define THREADS 256

// -------- device scratch (allocation-free rule: __device__ globals) --------
__device__ float g_x[NMAX * D];
__device__ float g_agg[NMAX * D];
__device__ float g_out[NMAX * D];
__device__ float g_z[NMAX * D];
__device__ float g_rx[NMAX * D];

// ---------------------------------------------------------------------------
// GEMM building blocks.
// Block tile: 128 rows x 128 cols, K chunked by 16. 256 threads, thread grid
// 16(tr) x 16(tc). Micro-tile 8x8 per thread, split as 2x2 blocks of 4x4:
//   rows: {tr*4..tr*4+3} and {64+tr*4..+3}, cols likewise with tc.
// SMEM: As[k][r] (transposed A chunk), Bs[k][c] (W chunk, row-major).
// ---------------------------------------------------------------------------

__device__ __forceinline__ void fma_8x8(float acc[8][8], float4 a0, float4 a1,
                                        float4 b0, float4 b1) {
    float av[8] = {a0.x, a0.y, a0.z, a0.w, a1.x, a1.y, a1.z, a1.w};
    float bv[8] = {b0.x, b0.y, b0.z, b0.w, b1.x, b1.y, b1.z, b1.w};
#pragma unroll
    for (int i = 0; i < 8; ++i)
#pragma unroll
        for (int j = 0; j < 8; ++j)
            acc[i][j] += av[i] * bv[j];
}

// Load A chunk [row0..row0+128) x [k0..k0+16) transposed into As[k][r].
__device__ __forceinline__ void load_As(const float* __restrict__ A, int row0,
                                        int Nrows, int k0, float* As, int tid) {
#pragma unroll
    for (int q = 0; q < 2; ++q) {
        int idx = tid + q * 256;       // 0..511
        int row = idx >> 2;            // 0..127
        int kq  = (idx & 3) << 2;      // 0,4,8,12
        float4 v = make_float4(0.f, 0.f, 0.f, 0.f);
        if (row0 + row < Nrows)
            v = reinterpret_cast<const float4*>(A)[(size_t)(row0 + row) * D4 + ((k0 + kq) >> 2)];
        As[(kq + 0) * 128 + row] = v.x;
        As[(kq + 1) * 128 + row] = v.y;
        As[(kq + 2) * 128 + row] = v.z;
        As[(kq + 3) * 128 + row] = v.w;
    }
}

// Load W chunk [k0..k0+16) x [0..128) into Bs[k][c] (direct copy, coalesced).
__device__ __forceinline__ void load_Bs(const float* __restrict__ W, int k0,
                                        float* Bs, int tid) {
#pragma unroll
    for (int q = 0; q < 2; ++q) {
        int idx = tid + q * 256;
        int k  = idx >> 5;
        int c4 = idx & 31;
        reinterpret_cast<float4*>(Bs)[k * 32 + c4] =
            reinterpret_cast<const float4*>(W)[(size_t)(k0 + k) * D4 + c4];
    }
}

__device__ __forceinline__ void inner16(const float* As, const float* Bs,
                                        int tr, int tc, float acc[8][8]) {
#pragma unroll
    for (int k = 0; k < BK; ++k) {
        float4 a0 = reinterpret_cast<const float4*>(As)[k * 32 + tr];
        float4 a1 = reinterpret_cast<const float4*>(As)[k * 32 + 16 + tr];
        float4 b0 = reinterpret_cast<const float4*>(Bs)[k * 32 + tc];
        float4 b1 = reinterpret_cast<const float4*>(Bs)[k * 32 + 16 + tc];
        fma_8x8(acc, a0, a1, b0, b1);
    }
}

// Full-K GEMM accumulate: acc += A[row0:+128, :] @ W
__device__ __forceinline__ void gemm_global(const float* __restrict__ A,
                                            const float* __restrict__ W,
                                            int row0, int Nrows,
                                            float* As, float* Bs,
                                            int tid, int tr, int tc,
                                            float acc[8][8]) {
    for (int kc = 0; kc < D; kc += BK) {
        load_As(A, row0, Nrows, kc, As, tid);
        load_Bs(W, kc, Bs, tid);
        __syncthreads();
        inner16(As, Bs, tr, tc, acc);
        __syncthreads();
    }
}

__device__ __forceinline__ float sigf(float x) { return 1.0f / (1.0f + expf(-x)); }

// ---------------------------------------------------------------------------
// Fused 2-layer MLP: O = relu(A @ W1 + b1) @ W2 + b2
// Mid result H is kept in SMEM (transposed, XOR-swizzled) — no global traffic.
// ---------------------------------------------------------------------------
__global__ void __launch_bounds__(THREADS, 2)
mlp2_kernel(const float* __restrict__ A,
            const float* __restrict__ W1, const float* __restrict__ b1,
            const float* __restrict__ W2, const float* __restrict__ b2,
            float* __restrict__ O, int Nrows)
{
    extern __shared__ float sm[];
    float* As = sm;                 // 16*128
    float* Bs = sm + BK * 128;      // 16*128
    float* Hs = sm + 2 * BK * 128;  // 128*128 floats, layout Hs4[c*32 + (r4 ^ ((c>>2)&7))]

    int tid = threadIdx.x;
    int tr = tid >> 4, tc = tid & 15;
    int row0 = blockIdx.x * 128;

    float acc[8][8];
#pragma unroll
    for (int i = 0; i < 8; ++i)
#pragma unroll
        for (int j = 0; j < 8; ++j) acc[i][j] = 0.f;

    // ---- GEMM1: A @ W1 ----
    gemm_global(A, W1, row0, Nrows, As, Bs, tid, tr, tc, acc);

    // ---- epilogue1: relu(acc + b1) -> Hs (transposed + swizzled) ----
#pragma unroll
    for (int j = 0; j < 8; ++j) {
        int c = (j < 4) ? (tc * 4 + j) : (64 + tc * 4 + (j - 4));
        float bb = __ldg(&b1[c]);
        int sw = (c >> 2) & 7;
        float4 v0, v1;
        v0.x = fmaxf(acc[0][j] + bb, 0.f);
        v0.y = fmaxf(acc[1][j] + bb, 0.f);
        v0.z = fmaxf(acc[2][j] + bb, 0.f);
        v0.w = fmaxf(acc[3][j] + bb, 0.f);
        v1.x = fmaxf(acc[4][j] + bb, 0.f);
        v1.y = fmaxf(acc[5][j] + bb, 0.f);
        v1.z = fmaxf(acc[6][j] + bb, 0.f);
        v1.w = fmaxf(acc[7][j] + bb, 0.f);
        reinterpret_cast<float4*>(Hs)[c * 32 + (tr ^ sw)]      = v0;
        reinterpret_cast<float4*>(Hs)[c * 32 + (tr ^ sw) + 16] = v1;
    }
    __syncthreads();

#pragma unroll
    for (int i = 0; i < 8; ++i)
#pragma unroll
        for (int j = 0; j < 8; ++j) acc[i][j] = 0.f;

    // ---- GEMM2: Hs @ W2 ----
    for (int kc = 0; kc < D; kc += BK) {
        load_Bs(W2, kc, Bs, tid);
        __syncthreads();
#pragma unroll
        for (int k = 0; k < BK; ++k) {
            int kk = kc + k;
            int sw = (kk >> 2) & 7;
            float4 a0 = reinterpret_cast<const float4*>(Hs)[kk * 32 + (tr ^ sw)];
            float4 a1 = reinterpret_cast<const float4*>(Hs)[kk * 32 + (tr ^ sw) + 16];
            float4 b0 = reinterpret_cast<const float4*>(Bs)[k * 32 + tc];
            float4 b1 = reinterpret_cast<const float4*>(Bs)[k * 32 + 16 + tc];
            fma_8x8(acc, a0, a1, b0, b1);
        }
        __syncthreads();
    }

    // ---- epilogue2: O = acc + b2 ----
    float bb0[4], bb1[4];
#pragma unroll
    for (int j = 0; j < 4; ++j) {
        bb0[j] = __ldg(&b2[tc * 4 + j]);
        bb1[j] = __ldg(&b2[64 + tc * 4 + j]);
    }
#pragma unroll
    for (int i = 0; i < 8; ++i) {
        int row = row0 + ((i < 4) ? (tr * 4 + i) : (64 + tr * 4 + (i - 4)));
        if (row < Nrows) {
            float4 o0 = make_float4(acc[i][0] + bb0[0], acc[i][1] + bb0[1],
                                    acc[i][2] + bb0[2], acc[i][3] + bb0[3]);
            float4 o1 = make_float4(acc[i][4] + bb1[0], acc[i][5] + bb1[1],
                                    acc[i][6] + bb1[2], acc[i][7] + bb1[3]);
            reinterpret_cast<float4*>(O)[(size_t)row * D4 + tc]      = o0;
            reinterpret_cast<float4*>(O)[(size_t)row * D4 + 16 + tc] = o1;
        }
    }
}

// ---------------------------------------------------------------------------
// Gate kernels: acc = A1 @ Wa + A2 @ Wb, then mode-specific epilogue.
//  MODE 0: g_z  = sigmoid(acc + ba + bb)
//  MODE 1: g_rx = sigmoid(acc + ba + bb) * g_x
//  MODE 2: O    = (1-g_z)*g_x + g_z*tanh(acc + ba + bb)
// ---------------------------------------------------------------------------
template <int MODE>
__global__ void __launch_bounds__(THREADS, 2)
gate_kernel(const float* __restrict__ A1, const float* __restrict__ Wa, const float* __restrict__ ba,
            const float* __restrict__ A2, const float* __restrict__ Wb, const float* __restrict__ bb_,
            float* __restrict__ O, int Nrows)
{
    __shared__ float As[BK * 128];
    __shared__ float Bs[BK * 128];
    int tid = threadIdx.x;
    int tr = tid >> 4, tc = tid & 15;
    int row0 = blockIdx.x * 128;

    float acc[8][8];
#pragma unroll
    for (int i = 0; i < 8; ++i)
#pragma unroll
        for (int j = 0; j < 8; ++j) acc[i][j] = 0.f;

    gemm_global(A1, Wa, row0, Nrows, As, Bs, tid, tr, tc, acc);
    gemm_global(A2, Wb, row0, Nrows, As, Bs, tid, tr, tc, acc);

    float bs0[4], bs1[4];
#pragma unroll
    for (int j = 0; j < 4; ++j) {
        bs0[j] = __ldg(&ba[tc * 4 + j]) + __ldg(&bb_[tc * 4 + j]);
        bs1[j] = __ldg(&ba[64 + tc * 4 + j]) + __ldg(&bb_[64 + tc * 4 + j]);
    }

#pragma unroll
    for (int i = 0; i < 8; ++i) {
        int row = row0 + ((i < 4) ? (tr * 4 + i) : (64 + tr * 4 + (i - 4)));
        if (row >= Nrows) continue;
        size_t p0 = (size_t)row * D4 + tc;
        size_t p1 = p0 + 16;
        float t0[4] = {acc[i][0] + bs0[0], acc[i][1] + bs0[1], acc[i][2] + bs0[2], acc[i][3] + bs0[3]};
        float t1[4] = {acc[i][4] + bs1[0], acc[i][5] + bs1[1], acc[i][6] + bs1[2], acc[i][7] + bs1[3]};

        if (MODE == 0) {
            float4 z0 = make_float4(sigf(t0[0]), sigf(t0[1]), sigf(t0[2]), sigf(t0[3]));
            float4 z1 = make_float4(sigf(t1[0]), sigf(t1[1]), sigf(t1[2]), sigf(t1[3]));
            reinterpret_cast<float4*>(g_z)[p0] = z0;
            reinterpret_cast<float4*>(g_z)[p1] = z1;
        } else if (MODE == 1) {
            float4 x0 = reinterpret_cast<const float4*>(g_x)[p0];
            float4 x1 = reinterpret_cast<const float4*>(g_x)[p1];
            float4 r0 = make_float4(sigf(t0[0]) * x0.x, sigf(t0[1]) * x0.y,
                                    sigf(t0[2]) * x0.z, sigf(t0[3]) * x0.w);
            float4 r1 = make_float4(sigf(t1[0]) * x1.x, sigf(t1[1]) * x1.y,
                                    sigf(t1[2]) * x1.z, sigf(t1[3]) * x1.w);
            reinterpret_cast<float4*>(g_rx)[p0] = r0;
            reinterpret_cast<float4*>(g_rx)[p1] = r1;
        } else {
            float4 x0 = reinterpret_cast<const float4*>(g_x)[p0];
            float4 x1 = reinterpret_cast<const float4*>(g_x)[p1];
            float4 z0 = reinterpret_cast<const float4*>(g_z)[p0];
            float4 z1 = reinterpret_cast<const float4*>(g_z)[p1];
            float4 o0, o1;
            o0.x = (1.f - z0.x) * x0.x + z0.x * tanhf(t0[0]);
            o0.y = (1.f - z0.y) * x0.y + z0.y * tanhf(t0[1]);
            o0.z = (1.f - z0.z) * x0.z + z0.z * tanhf(t0[2]);
            o0.w = (1.f - z0.w) * x0.w + z0.w * tanhf(t0[3]);
            o1.x = (1.f - z1.x) * x1.x + z1.x * tanhf(t1[0]);
            o1.y = (1.f - z1.y) * x1.y + z1.y * tanhf(t1[1]);
            o1.z = (1.f - z1.z) * x1.z + z1.z * tanhf(t1[2]);
            o1.w = (1.f - z1.w) * x1.w + z1.w * tanhf(t1[3]);
            reinterpret_cast<float4*>(O)[p0] = o0;
            reinterpret_cast<float4*>(O)[p1] = o1;
        }
    }
}

// ---------------------------------------------------------------------------
// Edge scatter: agg[rows[e]] += vals[e] * x[cols[e]]   (warp per edge)
// ---------------------------------------------------------------------------
__global__ void scatter_kernel(const int* __restrict__ rows, const int* __restrict__ cols,
                               const float* __restrict__ vals, const float* __restrict__ x,
                               float* __restrict__ agg, int E)
{
    int gw = (blockIdx.x * blockDim.x + threadIdx.x) >> 5;
    int lane = threadIdx.x & 31;
    int nw = (gridDim.x * blockDim.x) >> 5;
    for (int e = gw; e < E; e += nw) {
        int r = __ldg(&rows[e]);
        int c = __ldg(&cols[e]);
        float v = __ldg(&vals[e]);
        float4 xv = reinterpret_cast<const float4*>(x)[(size_t)c * D4 + lane];
        float* dst = agg + (size_t)r * D + lane * 4;
        atomicAdd(dst + 0, v * xv.x);
        atomicAdd(dst + 1, v * xv.y);
        atomicAdd(dst + 2, v * xv.z);
        atomicAdd(dst + 3, v * xv.w);
    }
}

__global__ void zero_kernel(float* __restrict__ p, int n4)
{
    int i = blockIdx.x * blockDim.x + threadIdx.x;
    if (i < n4) reinterpret_cast<float4*>(p)[i] = make_float4(0.f, 0.f, 0.f, 0.f);
}

// ---------------------------------------------------------------------------
extern "C" void kernel_launch(void* const* d_in, const int* in_sizes, int n_in,
                              void* d_out, int out_size)
{
    const float* x_in  = (const float*)d_in[0];
    const int*   rows  = (const int*)  d_in[1];
    const int*   cols  = (const int*)  d_in[2];
    const float* vals  = (const float*)d_in[3];
    const float* m1_W1 = (const float*)d_in[4];
    const float* m1_b1 = (const float*)d_in[5];
    const float* m1_W2 = (const float*)d_in[6];
    const float* m1_b2 = (const float*)d_in[7];
    const float* m2_W1 = (const float*)d_in[8];
    const float* m2_b1 = (const float*)d_in[9];
    const float* m2_W2 = (const float*)d_in[10];
    const float* m2_b2 = (const float*)d_in[11];
    const float* Wu1   = (const float*)d_in[12];
    const float* bu1   = (const float*)d_in[13];
    const float* Wu2   = (const float*)d_in[14];
    const float* bu2   = (const float*)d_in[15];
    const float* Wr1   = (const float*)d_in[16];
    const float* br1   = (const float*)d_in[17];
    const float* Wr2   = (const float*)d_in[18];
    const float* br2   = (const float*)d_in[19];
    const float* Wo1   = (const float*)d_in[20];
    const float* bo1   = (const float*)d_in[21];
    const float* Wo2   = (const float*)d_in[22];
    const float* bo2   = (const float*)d_in[23];

    int N = in_sizes[0] / D;
    int E = in_sizes[1];

    float *px, *pagg, *pout, *prx;
    cudaGetSymbolAddress((void**)&px,   g_x);
    cudaGetSymbolAddress((void**)&pagg, g_agg);
    cudaGetSymbolAddress((void**)&pout, g_out);
    cudaGetSymbolAddress((void**)&prx,  g_rx);

    int smem_mlp = (2 * BK * 128 + 128 * 128) * (int)sizeof(float);  // 81920 B
    cudaFuncSetAttribute(mlp2_kernel, cudaFuncAttributeMaxDynamicSharedMemorySize, smem_mlp);

    int nblk = (N + 127) / 128;
    int n4 = N * D / 4;

    zero_kernel<<<(n4 + 255) / 256, 256>>>(pagg, n4);
    mlp2_kernel<<<nblk, THREADS, smem_mlp>>>(x_in, m1_W1, m1_b1, m1_W2, m1_b2, px, N);
    scatter_kernel<<<2048, 256>>>(rows, cols, vals, px, pagg, E);
    mlp2_kernel<<<nblk, THREADS, smem_mlp>>>(pagg, m2_W1, m2_b1, m2_W2, m2_b2, pout, N);
    gate_kernel<0><<<nblk, THREADS>>>(pout, Wu1, bu1, px, Wu2, bu2, nullptr, N);
    gate_kernel<1><<<nblk, THREADS>>>(pout, Wr1, br1, px, Wr2, br2, nullptr, N);
    gate_kernel<2><<<nblk, THREADS>>>(pout, Wo1, bo1, prx, Wo2, bo2, (float*)d_out, N);
}